// round 4
// baseline (speedup 1.0000x reference)
#include <cuda_runtime.h>
#include <stdint.h>

// ---------------------------------------------------------------------------
// AdaptiveLogits: adaptive-softmax logits on GB300 (sm_103a).
//   out = [ head_logits (B x 2002) | logits0 (B x 18000) | logits1 (B x 80001) ]
// Strategy: compact active rows per tail bucket, run fp32x2 (FFMA2) tiled
// GEMMs only on active rows (software-pipelined global->smem staging),
// scatter results, zero-fill inactive rows exactly once (vectorized).
// ---------------------------------------------------------------------------

#define C0 2000
#define C1 20000
#define C2 100001
#define HID 1024
#define HID_RF 256
#define BATCH_MAX 4096

#define N_HEAD (C0 + 2)   /* 2002  */
#define N_T0   (C1 - C0)  /* 18000 */
#define N_T1   (C2 - C1)  /* 80001 */

// ---- device scratch (static: no allocation allowed) -----------------------
__device__ int g_cnt0;
__device__ int g_cnt1;
__device__ int g_rows0[BATCH_MAX];
__device__ int g_rows1[BATCH_MAX];
__device__ __align__(16) float g_h0[(size_t)BATCH_MAX * HID];     // 16 MB
__device__ __align__(16) float g_h1[(size_t)BATCH_MAX * HID_RF];  //  4 MB

// ---- bucket classification ------------------------------------------------
__global__ void init_counts_k() { g_cnt0 = 0; g_cnt1 = 0; }

__global__ void classify_k(const int* __restrict__ targets, int B) {
    int b = blockIdx.x * blockDim.x + threadIdx.x;
    if (b >= B) return;
    int t = targets[b];
    if (t >= C0 && t < C1) {
        int p = atomicAdd(&g_cnt0, 1);
        g_rows0[p] = b;
    } else if (t >= C1) {
        int p = atomicAdd(&g_cnt1, 1);
        g_rows1[p] = b;
    }
}

// ---- zero-fill inactive rows (written exactly once; active rows are
//      fully overwritten by the GEMM scatter epilogue) ----------------------
__global__ void zero0_k(const int* __restrict__ targets, float* __restrict__ out0) {
    int b = blockIdx.x;
    int t = targets[b];
    if (t >= C0 && t < C1) return;  // active row: GEMM writes it
    // N_T0 = 18000, divisible by 4; row starts are 16B-aligned (18000 % 4 == 0)
    float4* p = reinterpret_cast<float4*>(out0 + (long long)b * N_T0);
    const float4 z = make_float4(0.f, 0.f, 0.f, 0.f);
    for (int i = threadIdx.x; i < N_T0 / 4; i += blockDim.x) p[i] = z;
}

__global__ void zero1_k(const int* __restrict__ targets, float* __restrict__ out1) {
    int b = blockIdx.x;
    int t = targets[b];
    if (t >= C1) return;            // active row: GEMM writes it
    long long base = (long long)b * N_T1;  // 80001 is odd: per-row misalignment
    float* p = out1 + base;
    int lead = (int)((4 - (base & 3)) & 3);        // scalars until 16B aligned
    int nv = (N_T1 - lead) / 4;                    // float4 body count
    int tail_start = lead + nv * 4;
    if (threadIdx.x < lead) p[threadIdx.x] = 0.f;
    float4* pv = reinterpret_cast<float4*>(p + lead);
    const float4 z = make_float4(0.f, 0.f, 0.f, 0.f);
    for (int i = threadIdx.x; i < nv; i += blockDim.x) pv[i] = z;
    for (int i = tail_start + (int)threadIdx.x; i < N_T1; i += blockDim.x) p[i] = 0.f;
}

// ---- fp32x2 tiled GEMM (software-pipelined) -------------------------------
// C[i][n] = sum_k A[rowA(i)][k] * B[n][k]      (B row-major [N, ldb])
//   rowA(i) = rowsA ? rowsA[i] : i   (gather)
//   rowC(i) = rowsC ? rowsC[i] : i   (scatter)
//   M_eff   = pcnt ? *pcnt : Mmax    (device-side dynamic M, graph-safe)
//   head special-case: columns n >= nb1 come from B2 (tail_vectors).
// Tile: BM=64 x BN=128, BK=16, 256 threads; each thread 4 rows x 4 f32x2
// column-pairs (pairs interleaved at stride 32 -> conflict-free LDS.64).
#define BM 64
#define BN 128
#define BK 16

__global__ __launch_bounds__(256)
void gemm_f32x2(const float* __restrict__ A, int lda,
                const int* __restrict__ rowsA,
                const int* __restrict__ pcnt, int Mmax,
                const float* __restrict__ B, const float* __restrict__ B2,
                int nb1, int ldb,
                int N, int K,
                float* __restrict__ C, int ldc,
                const int* __restrict__ rowsC) {
    const int Meff = pcnt ? *pcnt : Mmax;
    const int m0 = blockIdx.y * BM;
    if (m0 >= Meff) return;
    const int n0 = blockIdx.x * BN;

    __shared__ float As[BK][BM];
    __shared__ __align__(16) float Bs[BK][BN];

    const int tid = threadIdx.x;

    // A tile load mapping: 64 rows x 16 k, one float4 along K per thread
    const int a_m = tid >> 2;            // 0..63
    const int a_k = (tid & 3) * 4;       // 0,4,8,12
    const int ai_idx = m0 + a_m;
    int arow = 0;
    if (ai_idx < Meff) arow = rowsA ? rowsA[ai_idx] : ai_idx;
    const float* Aptr = A + (long long)arow * lda + a_k;

    // B tile load mapping: 128 cols x 16 k, two float4 along K per thread
    const int b_n = tid >> 1;            // 0..127
    const int b_k = (tid & 1) * 8;       // 0 or 8
    const int bn = n0 + b_n;
    const float* Bptr = nullptr;
    if (bn < N) {
        if (B2 != nullptr && bn >= nb1)
            Bptr = B2 + (long long)(bn - nb1) * ldb + b_k;
        else
            Bptr = B + (long long)bn * ldb + b_k;
    }

    // compute mapping: 4 rows, 4 column-PAIRS at stride 32 (conflict-free)
    const int tm  = (tid >> 4) * 4;      // 0..60 step 4
    const int tnc = (tid & 15) * 2;      // 0..30 step 2

    unsigned long long acc[4][4];
#pragma unroll
    for (int r = 0; r < 4; ++r)
#pragma unroll
        for (int c = 0; c < 4; ++c) acc[r][c] = 0ull;

    const float4 fz = make_float4(0.f, 0.f, 0.f, 0.f);

    // prefetch tile 0 into registers
    float4 av = *reinterpret_cast<const float4*>(Aptr);
    float4 bv0 = Bptr ? *reinterpret_cast<const float4*>(Bptr)     : fz;
    float4 bv1 = Bptr ? *reinterpret_cast<const float4*>(Bptr + 4) : fz;

    for (int kt = 0; kt < K; kt += BK) {
        // fill smem from staged registers
        As[a_k + 0][a_m] = av.x;
        As[a_k + 1][a_m] = av.y;
        As[a_k + 2][a_m] = av.z;
        As[a_k + 3][a_m] = av.w;
        Bs[b_k + 0][b_n] = bv0.x;
        Bs[b_k + 1][b_n] = bv0.y;
        Bs[b_k + 2][b_n] = bv0.z;
        Bs[b_k + 3][b_n] = bv0.w;
        Bs[b_k + 4][b_n] = bv1.x;
        Bs[b_k + 5][b_n] = bv1.y;
        Bs[b_k + 6][b_n] = bv1.z;
        Bs[b_k + 7][b_n] = bv1.w;
        __syncthreads();

        // issue next tile's global loads BEFORE compute (latency overlap)
        const int kn = kt + BK;
        if (kn < K) {
            av  = *reinterpret_cast<const float4*>(Aptr + kn);
            bv0 = Bptr ? *reinterpret_cast<const float4*>(Bptr + kn)     : fz;
            bv1 = Bptr ? *reinterpret_cast<const float4*>(Bptr + kn + 4) : fz;
        }

#pragma unroll
        for (int k = 0; k < BK; ++k) {
            unsigned long long a2[4], b2[4];
#pragma unroll
            for (int r = 0; r < 4; ++r) {
                unsigned int av32 = __float_as_uint(As[k][tm + r]);
                asm("mov.b64 %0, {%1, %1};" : "=l"(a2[r]) : "r"(av32));
            }
#pragma unroll
            for (int c = 0; c < 4; ++c)
                b2[c] = *reinterpret_cast<const unsigned long long*>(
                    &Bs[k][tnc + c * 32]);
#pragma unroll
            for (int r = 0; r < 4; ++r)
#pragma unroll
                for (int c = 0; c < 4; ++c)
                    asm("fma.rn.f32x2 %0, %1, %2, %0;"
                        : "+l"(acc[r][c])
                        : "l"(a2[r]), "l"(b2[c]));
        }
        __syncthreads();
    }

    // epilogue: scatter with M/N guards (scalar stores; N_T1 rows are odd-offset)
#pragma unroll
    for (int r = 0; r < 4; ++r) {
        int i = m0 + tm + r;
        if (i >= Meff) break;
        long long orow = rowsC ? (long long)rowsC[i] : (long long)i;
        float* Crow = C + orow * ldc;
#pragma unroll
        for (int c = 0; c < 4; ++c) {
            unsigned int lo, hi;
            asm("mov.b64 {%0, %1}, %2;" : "=r"(lo), "=r"(hi) : "l"(acc[r][c]));
            int col = n0 + tnc + c * 32;
            if (col < N)     Crow[col]     = __uint_as_float(lo);
            if (col + 1 < N) Crow[col + 1] = __uint_as_float(hi);
        }
    }
}

// ---------------------------------------------------------------------------
extern "C" void kernel_launch(void* const* d_in, const int* in_sizes, int n_in,
                              void* d_out, int out_size) {
    const float* hidden  = (const float*)d_in[0];  // (B, 1024)
    const int*   targets = (const int*)  d_in[1];  // (B,)
    const float* cand    = (const float*)d_in[2];  // (100001, 1024)
    const float* tailv   = (const float*)d_in[3];  // (2, 1024)
    const float* down0   = (const float*)d_in[4];  // (1024, 1024)
    const float* down1   = (const float*)d_in[5];  // (256, 1024)
    const float* dec1    = (const float*)d_in[6];  // (80001, 256)
    float* out = (float*)d_out;

    const int B = in_sizes[1];  // 4096

    float* outH = out;
    float* out0 = outH + (size_t)B * N_HEAD;
    float* out1 = out0 + (size_t)B * N_T0;

    // device-global scratch addresses (host-side query; graph-capture safe)
    int *p_cnt0, *p_cnt1, *p_rows0, *p_rows1;
    float *p_h0, *p_h1;
    cudaGetSymbolAddress((void**)&p_cnt0,  g_cnt0);
    cudaGetSymbolAddress((void**)&p_cnt1,  g_cnt1);
    cudaGetSymbolAddress((void**)&p_rows0, g_rows0);
    cudaGetSymbolAddress((void**)&p_rows1, g_rows1);
    cudaGetSymbolAddress((void**)&p_h0,    g_h0);
    cudaGetSymbolAddress((void**)&p_h1,    g_h1);

    const int BIG = 1 << 30;
    const int mb = (B + BM - 1) / BM;  // 64

    // 1) reset + classify rows into tail buckets
    init_counts_k<<<1, 1>>>();
    classify_k<<<(B + 255) / 256, 256>>>(targets, B);

    // 2) head: hidden @ concat(cand[:2000], tail_vectors)^T  -> (B, 2002)
    gemm_f32x2<<<dim3((N_HEAD + BN - 1) / BN, mb), 256>>>(
        hidden, HID, nullptr, nullptr, B,
        cand, tailv, C0, HID, N_HEAD, HID,
        outH, N_HEAD, nullptr);

    // 3) tail0 down-proj on gathered active rows: (cnt0, 1024)
    gemm_f32x2<<<dim3(HID / BN, mb), 256>>>(
        hidden, HID, p_rows0, p_cnt0, B,
        down0, nullptr, BIG, HID, HID, HID,
        p_h0, HID, nullptr);

    // 4) tail0 logits: h0c @ cand[2000:20000]^T, scatter -> out0
    gemm_f32x2<<<dim3((N_T0 + BN - 1) / BN, mb), 256>>>(
        p_h0, HID, nullptr, p_cnt0, B,
        cand + (size_t)C0 * HID, nullptr, BIG, HID, N_T0, HID,
        out0, N_T0, p_rows0);

    // 5) tail1 down-proj on gathered active rows: (cnt1, 256)
    gemm_f32x2<<<dim3(HID_RF / BN, mb), 256>>>(
        hidden, HID, p_rows1, p_cnt1, B,
        down1, nullptr, BIG, HID, HID_RF, HID,
        p_h1, HID_RF, nullptr);

    // 6) tail1 logits: h1c @ decode1^T (K=256), scatter -> out1
    gemm_f32x2<<<dim3((N_T1 + BN - 1) / BN, mb), 256>>>(
        p_h1, HID_RF, nullptr, p_cnt1, B,
        dec1, nullptr, BIG, HID_RF, N_T1, HID_RF,
        out1, N_T1, p_rows1);

    // 7) zero inactive rows exactly once (vectorized)
    zero0_k<<<B, 256>>>(targets, out0);
    zero1_k<<<B, 256>>>(targets, out1);

    (void)n_in; (void)out_size;
}

// round 9
// speedup vs baseline: 1.7981x; 1.7981x over previous
#include <cuda_runtime.h>
#include <cuda_bf16.h>
#include <stdint.h>

// ---------------------------------------------------------------------------
// AdaptiveLogits on GB300 — mma.sync (HMMA fallback) bf16 hi/lo-split GEMMs.
// tcgen05 is NOT available: harness ptxas targets sm_103 (no 'a' suffix).
//   out = [ head (B x 2002) | logits0 (B x 18000) | logits1 (B x 80001) ]
// fp32 = hi + lo (bf16 each); C = Ahi*Bhi + Ahi*Blo + Alo*Bhi (err ~2^-16).
// ---------------------------------------------------------------------------

#define C0 2000
#define C1 20000
#define C2 100001
#define HID 1024
#define HID_RF 256
#define BATCH_MAX 4096

#define N_HEAD (C0 + 2)   /* 2002  */
#define N_T0   (C1 - C0)  /* 18000 */
#define N_T1   (C2 - C1)  /* 80001 */

typedef __nv_bfloat16 bf16;

// ---- device scratch (static; allocation forbidden) ------------------------
__device__ int g_cnt0;
__device__ int g_cnt1;
__device__ int g_rows0[BATCH_MAX];
__device__ int g_rows1[BATCH_MAX];

__device__ __align__(16) bf16 g_hid_hi[(size_t)BATCH_MAX * HID];
__device__ __align__(16) bf16 g_hid_lo[(size_t)BATCH_MAX * HID];
__device__ __align__(16) bf16 g_h0_hi[(size_t)BATCH_MAX * HID];
__device__ __align__(16) bf16 g_h0_lo[(size_t)BATCH_MAX * HID];
__device__ __align__(16) bf16 g_h1_hi[(size_t)BATCH_MAX * HID_RF];
__device__ __align__(16) bf16 g_h1_lo[(size_t)BATCH_MAX * HID_RF];
__device__ __align__(16) bf16 g_wh_hi[(size_t)N_HEAD * HID];
__device__ __align__(16) bf16 g_wh_lo[(size_t)N_HEAD * HID];
__device__ __align__(16) bf16 g_ct0_hi[(size_t)N_T0 * HID];
__device__ __align__(16) bf16 g_ct0_lo[(size_t)N_T0 * HID];
__device__ __align__(16) bf16 g_d1_hi[(size_t)N_T1 * HID_RF];
__device__ __align__(16) bf16 g_d1_lo[(size_t)N_T1 * HID_RF];
__device__ __align__(16) bf16 g_dn0_hi[(size_t)HID * HID];
__device__ __align__(16) bf16 g_dn0_lo[(size_t)HID * HID];
__device__ __align__(16) bf16 g_dn1_hi[(size_t)HID_RF * HID];
__device__ __align__(16) bf16 g_dn1_lo[(size_t)HID_RF * HID];

// ---- helpers ---------------------------------------------------------------
__device__ __forceinline__ uint32_t smem_u32(const void* p) {
    uint32_t a;
    asm("{ .reg .u64 t; cvta.to.shared.u64 t, %1; cvt.u32.u64 %0, t; }"
        : "=r"(a) : "l"(p));
    return a;
}

#define LDM4(r, a) \
    asm volatile("ldmatrix.sync.aligned.m8n8.x4.shared.b16 {%0,%1,%2,%3}, [%4];" \
        : "=r"((r)[0]), "=r"((r)[1]), "=r"((r)[2]), "=r"((r)[3]) : "r"(a))

#define MMA16816(d, a, b0v, b1v) \
    asm volatile("mma.sync.aligned.m16n8k16.row.col.f32.bf16.bf16.f32 " \
        "{%0,%1,%2,%3}, {%4,%5,%6,%7}, {%8,%9}, {%0,%1,%2,%3};" \
        : "+f"((d)[0]), "+f"((d)[1]), "+f"((d)[2]), "+f"((d)[3]) \
        : "r"((a)[0]), "r"((a)[1]), "r"((a)[2]), "r"((a)[3]), \
          "r"(b0v), "r"(b1v))

// ---- bucket classification -------------------------------------------------
__global__ void init_counts_k() { g_cnt0 = 0; g_cnt1 = 0; }

__global__ void classify_k(const int* __restrict__ targets, int B) {
    int b = blockIdx.x * blockDim.x + threadIdx.x;
    if (b >= B) return;
    int t = targets[b];
    if (t >= C0 && t < C1) g_rows0[atomicAdd(&g_cnt0, 1)] = b;
    else if (t >= C1)      g_rows1[atomicAdd(&g_cnt1, 1)] = b;
}

// ---- fp32 -> bf16 hi/lo split ----------------------------------------------
__global__ void conv_k(const float* __restrict__ src,
                       bf16* __restrict__ hi, bf16* __restrict__ lo, int n4) {
    int i = blockIdx.x * blockDim.x + threadIdx.x;
    if (i >= n4) return;
    float4 v = reinterpret_cast<const float4*>(src)[i];
    bf16 hx = __float2bfloat16(v.x), hy = __float2bfloat16(v.y);
    bf16 hz = __float2bfloat16(v.z), hw = __float2bfloat16(v.w);
    bf16 lx = __float2bfloat16(v.x - __bfloat162float(hx));
    bf16 ly = __float2bfloat16(v.y - __bfloat162float(hy));
    bf16 lz = __float2bfloat16(v.z - __bfloat162float(hz));
    bf16 lw = __float2bfloat16(v.w - __bfloat162float(hw));
    __nv_bfloat162* H = reinterpret_cast<__nv_bfloat162*>(hi);
    __nv_bfloat162* L = reinterpret_cast<__nv_bfloat162*>(lo);
    H[2 * i]     = __halves2bfloat162(hx, hy);
    H[2 * i + 1] = __halves2bfloat162(hz, hw);
    L[2 * i]     = __halves2bfloat162(lx, ly);
    L[2 * i + 1] = __halves2bfloat162(lz, lw);
}

// ---- zero-fill inactive rows -----------------------------------------------
__global__ void zero0_k(const int* __restrict__ targets, float* __restrict__ out0) {
    int b = blockIdx.x;
    int t = targets[b];
    if (t >= C0 && t < C1) return;
    float4* p = reinterpret_cast<float4*>(out0 + (long long)b * N_T0);
    const float4 z = make_float4(0.f, 0.f, 0.f, 0.f);
    for (int i = threadIdx.x; i < N_T0 / 4; i += blockDim.x) p[i] = z;
}

__global__ void zero1_k(const int* __restrict__ targets, float* __restrict__ out1) {
    int b = blockIdx.x;
    int t = targets[b];
    if (t >= C1) return;
    long long base = (long long)b * N_T1;
    float* p = out1 + base;
    int lead = (int)((4 - (base & 3)) & 3);
    int nv = (N_T1 - lead) / 4;
    int tail_start = lead + nv * 4;
    if (threadIdx.x < (unsigned)lead) p[threadIdx.x] = 0.f;
    float4* pv = reinterpret_cast<float4*>(p + lead);
    const float4 z = make_float4(0.f, 0.f, 0.f, 0.f);
    for (int i = threadIdx.x; i < nv; i += blockDim.x) pv[i] = z;
    for (int i = tail_start + (int)threadIdx.x; i < N_T1; i += blockDim.x) p[i] = 0.f;
}

// ---- mma.sync bf16-split GEMM ----------------------------------------------
// C[i][n] = sum_k A[rowA(i)][k] * B[n][k]  via Ahi*Bhi + Ahi*Blo + Alo*Bhi.
// Tile BM=128 x BN=64, BK=32 bf16/stage, 256 thr (8 warps 4x2, warp 32x32).
// ldmatrix from padded smem (stride 40 bf16 = 20 banks, conflict-free).
#define BM 128
#define BN 64
#define LDT 40   /* padded smem row stride, bf16 units */

__global__ __launch_bounds__(256)
void gemm_mma(const bf16* __restrict__ Ahi, const bf16* __restrict__ Alo, int lda,
              const int* __restrict__ rowsA, const int* __restrict__ pcnt, int Mmax,
              const bf16* __restrict__ Bhi, const bf16* __restrict__ Blo,
              int ldb, int N, int K,
              float* __restrict__ C, long long ldc, const int* __restrict__ rowsC,
              bf16* __restrict__ outHi, bf16* __restrict__ outLo) {
    const int Meff = pcnt ? *pcnt : Mmax;
    const int m0 = blockIdx.y * BM;
    if (m0 >= Meff) return;
    const int n0 = blockIdx.x * BN;

    __shared__ __align__(16) bf16 sAh[BM * LDT];
    __shared__ __align__(16) bf16 sAl[BM * LDT];
    __shared__ __align__(16) bf16 sBh[BN * LDT];
    __shared__ __align__(16) bf16 sBl[BN * LDT];

    const int tid = threadIdx.x;
    const int lid = tid & 31;
    const int wid = tid >> 5;

    // ---- staging mapping ----
    // A: thread -> row tid>>1 (0..127), 32B half (tid&1)
    const int srow = tid >> 1, sseg = tid & 1;
    int ai = m0 + srow;
    long long arow = 0;
    if (ai < Meff) arow = rowsA ? rowsA[ai] : ai;
    const bf16* aH = Ahi + arow * lda + sseg * 16;
    const bf16* aL = Alo + arow * lda + sseg * 16;
    // B: thread -> row tid>>2 (0..63), 16B quarter (tid&3)
    const int brow = tid >> 2, bseg = tid & 3;
    int bn = n0 + brow; if (bn >= N) bn = 0;
    const bf16* bH = Bhi + (long long)bn * ldb + bseg * 8;
    const bf16* bL = Blo + (long long)bn * ldb + bseg * 8;

    const int sa_off = srow * LDT + sseg * 16;  // bf16 units
    const int sb_off = brow * LDT + bseg * 8;

    // ---- compute mapping ----
    const int wm = wid >> 1;          // 0..3  (m warp, 32 rows)
    const int wn = wid & 1;           // 0..1  (n warp, 32 cols)
    const int lrow = lid & 15;
    const int lsel = lid >> 4;        // 0/1 -> +8 k columns

    const uint32_t aHb = smem_u32(sAh), aLb = smem_u32(sAl);
    const uint32_t bHb = smem_u32(sBh), bLb = smem_u32(sBl);
    // ldmatrix address: tile at (row0, kc): (row0+lrow)*LDT + kc + lsel*8
    const uint32_t a_lane = (uint32_t)((wm * 32 + lrow) * LDT + lsel * 8) * 2;
    const uint32_t b_lane = (uint32_t)((wn * 32 + lrow) * LDT + lsel * 8) * 2;

    float acc[2][4][4];
#pragma unroll
    for (int mi = 0; mi < 2; ++mi)
#pragma unroll
        for (int nj = 0; nj < 4; ++nj)
#pragma unroll
            for (int e = 0; e < 4; ++e) acc[mi][nj][e] = 0.f;

    // prefetch stage 0
    uint4 pah0 = *reinterpret_cast<const uint4*>(aH);
    uint4 pah1 = *reinterpret_cast<const uint4*>(aH + 8);
    uint4 pal0 = *reinterpret_cast<const uint4*>(aL);
    uint4 pal1 = *reinterpret_cast<const uint4*>(aL + 8);
    uint4 pbh  = *reinterpret_cast<const uint4*>(bH);
    uint4 pbl  = *reinterpret_cast<const uint4*>(bL);

    const int niter = K >> 5;  // BK=32
    for (int it = 0; it < niter; ++it) {
        if (it) __syncthreads();  // previous compute done before overwrite
        *reinterpret_cast<uint4*>(sAh + sa_off)     = pah0;
        *reinterpret_cast<uint4*>(sAh + sa_off + 8) = pah1;
        *reinterpret_cast<uint4*>(sAl + sa_off)     = pal0;
        *reinterpret_cast<uint4*>(sAl + sa_off + 8) = pal1;
        *reinterpret_cast<uint4*>(sBh + sb_off)     = pbh;
        *reinterpret_cast<uint4*>(sBl + sb_off)     = pbl;
        __syncthreads();

        const int kn = (it + 1) << 5;
        if (kn < K) {  // prefetch next stage (overlaps compute)
            pah0 = *reinterpret_cast<const uint4*>(aH + kn);
            pah1 = *reinterpret_cast<const uint4*>(aH + kn + 8);
            pal0 = *reinterpret_cast<const uint4*>(aL + kn);
            pal1 = *reinterpret_cast<const uint4*>(aL + kn + 8);
            pbh  = *reinterpret_cast<const uint4*>(bH + kn);
            pbl  = *reinterpret_cast<const uint4*>(bL + kn);
        }

#pragma unroll
        for (int kc = 0; kc < 32; kc += 16) {
            uint32_t ah[8], al[8], bh[8], bl[8];
            const uint32_t kb = (uint32_t)kc * 2;
            LDM4(ah + 0, aHb + a_lane + kb);
            LDM4(ah + 4, aHb + a_lane + kb + (uint32_t)(16 * LDT * 2));
            LDM4(al + 0, aLb + a_lane + kb);
            LDM4(al + 4, aLb + a_lane + kb + (uint32_t)(16 * LDT * 2));
            LDM4(bh + 0, bHb + b_lane + kb);
            LDM4(bh + 4, bHb + b_lane + kb + (uint32_t)(16 * LDT * 2));
            LDM4(bl + 0, bLb + b_lane + kb);
            LDM4(bl + 4, bLb + b_lane + kb + (uint32_t)(16 * LDT * 2));
            // B x4 over n16 yields regs {n0:b0, n1:b0, n0:b1, n1:b1}
#pragma unroll
            for (int mi = 0; mi < 2; ++mi) {
#pragma unroll
                for (int nj = 0; nj < 4; ++nj) {
                    const int g = (nj >> 1) * 4, s = nj & 1;
                    MMA16816(acc[mi][nj], ah + mi * 4, bh[g + s], bh[g + 2 + s]);
                    MMA16816(acc[mi][nj], ah + mi * 4, bl[g + s], bl[g + 2 + s]);
                    MMA16816(acc[mi][nj], al + mi * 4, bh[g + s], bh[g + 2 + s]);
                }
            }
        }
    }

    // ---- epilogue ----
    const int col0 = n0 + wn * 32 + (lid & 3) * 2;
#pragma unroll
    for (int mi = 0; mi < 2; ++mi) {
        const int i0 = m0 + wm * 32 + mi * 16 + (lid >> 2);
        const int i1 = i0 + 8;
#pragma unroll
        for (int half = 0; half < 2; ++half) {
            const int i = half ? i1 : i0;
            if (i >= Meff) continue;
            if (outHi) {
                long long base = (long long)i * ldc;
#pragma unroll
                for (int nj = 0; nj < 4; ++nj) {
                    int col = col0 + nj * 8;
#pragma unroll
                    for (int e = 0; e < 2; ++e) {
                        if (col + e < N) {
                            float v = acc[mi][nj][half * 2 + e];
                            bf16 h = __float2bfloat16(v);
                            outHi[base + col + e] = h;
                            outLo[base + col + e] =
                                __float2bfloat16(v - __bfloat162float(h));
                        }
                    }
                }
            } else {
                long long orow = rowsC ? (long long)rowsC[i] : (long long)i;
                float* Crow = C + orow * ldc;
#pragma unroll
                for (int nj = 0; nj < 4; ++nj) {
                    int col = col0 + nj * 8;
                    if (col + 1 < N) {
                        Crow[col]     = acc[mi][nj][half * 2 + 0];
                        Crow[col + 1] = acc[mi][nj][half * 2 + 1];
                    } else {
                        if (col < N) Crow[col] = acc[mi][nj][half * 2 + 0];
                    }
                }
            }
        }
    }
}

// ---------------------------------------------------------------------------
extern "C" void kernel_launch(void* const* d_in, const int* in_sizes, int n_in,
                              void* d_out, int out_size) {
    const float* hidden  = (const float*)d_in[0];  // (B, 1024)
    const int*   targets = (const int*)  d_in[1];  // (B,)
    const float* cand    = (const float*)d_in[2];  // (100001, 1024)
    const float* tailv   = (const float*)d_in[3];  // (2, 1024)
    const float* down0   = (const float*)d_in[4];  // (1024, 1024)
    const float* down1   = (const float*)d_in[5];  // (256, 1024)
    const float* dec1    = (const float*)d_in[6];  // (80001, 256)
    float* out = (float*)d_out;

    const int B = in_sizes[1];  // 4096

    float* outH = out;
    float* out0 = outH + (size_t)B * N_HEAD;
    float* out1 = out0 + (size_t)B * N_T0;

    int *p_cnt0, *p_cnt1, *p_rows0, *p_rows1;
    bf16 *hid_hi, *hid_lo, *h0_hi, *h0_lo, *h1_hi, *h1_lo;
    bf16 *wh_hi, *wh_lo, *ct0_hi, *ct0_lo, *d1_hi, *d1_lo;
    bf16 *dn0_hi, *dn0_lo, *dn1_hi, *dn1_lo;
#define SYM(p, s) cudaGetSymbolAddress((void**)&(p), s)
    SYM(p_cnt0, g_cnt0);   SYM(p_cnt1, g_cnt1);
    SYM(p_rows0, g_rows0); SYM(p_rows1, g_rows1);
    SYM(hid_hi, g_hid_hi); SYM(hid_lo, g_hid_lo);
    SYM(h0_hi, g_h0_hi);   SYM(h0_lo, g_h0_lo);
    SYM(h1_hi, g_h1_hi);   SYM(h1_lo, g_h1_lo);
    SYM(wh_hi, g_wh_hi);   SYM(wh_lo, g_wh_lo);
    SYM(ct0_hi, g_ct0_hi); SYM(ct0_lo, g_ct0_lo);
    SYM(d1_hi, g_d1_hi);   SYM(d1_lo, g_d1_lo);
    SYM(dn0_hi, g_dn0_hi); SYM(dn0_lo, g_dn0_lo);
    SYM(dn1_hi, g_dn1_hi); SYM(dn1_lo, g_dn1_lo);
#undef SYM

    const int mb = (B + BM - 1) / BM;  // 32

    // 1) classify rows
    init_counts_k<<<1, 1>>>();
    classify_k<<<(B + 255) / 256, 256>>>(targets, B);

    // 2) split-convert weights + hidden to bf16 hi/lo
    {
        auto cv = [](const float* s, bf16* h, bf16* l, long long n) {
            int n4 = (int)(n / 4);
            conv_k<<<(n4 + 255) / 256, 256>>>(s, h, l, n4);
        };
        cv(cand, wh_hi, wh_lo, (long long)C0 * HID);
        cv(tailv, wh_hi + (size_t)C0 * HID, wh_lo + (size_t)C0 * HID, 2LL * HID);
        cv(cand + (size_t)C0 * HID, ct0_hi, ct0_lo, (long long)N_T0 * HID);
        cv(dec1, d1_hi, d1_lo, (long long)N_T1 * HID_RF);
        cv(down0, dn0_hi, dn0_lo, (long long)HID * HID);
        cv(down1, dn1_hi, dn1_lo, (long long)HID_RF * HID);
        cv(hidden, hid_hi, hid_lo, (long long)B * HID);
    }

    // 3) head: hidden @ concat(cand[:2000], tailv)^T -> outH (B x 2002)
    gemm_mma<<<dim3((N_HEAD + BN - 1) / BN, mb), 256>>>(
        hid_hi, hid_lo, HID, nullptr, nullptr, B,
        wh_hi, wh_lo, HID, N_HEAD, HID,
        outH, (long long)N_HEAD, nullptr, nullptr, nullptr);

    // 4) tail0 down-proj (gather rows0) -> h0 hi/lo (dense, cnt0 x 1024)
    gemm_mma<<<dim3(HID / BN, mb), 256>>>(
        hid_hi, hid_lo, HID, p_rows0, p_cnt0, B,
        dn0_hi, dn0_lo, HID, HID, HID,
        nullptr, (long long)HID, nullptr, h0_hi, h0_lo);

    // 5) tail0 logits: h0 @ cand[2000:20000]^T, scatter rows0 -> out0
    gemm_mma<<<dim3((N_T0 + BN - 1) / BN, mb), 256>>>(
        h0_hi, h0_lo, HID, nullptr, p_cnt0, B,
        ct0_hi, ct0_lo, HID, N_T0, HID,
        out0, (long long)N_T0, p_rows0, nullptr, nullptr);

    // 6) tail1 down-proj (gather rows1) -> h1 hi/lo (dense, cnt1 x 256)
    gemm_mma<<<dim3(HID_RF / BN, mb), 256>>>(
        hid_hi, hid_lo, HID, p_rows1, p_cnt1, B,
        dn1_hi, dn1_lo, HID, HID_RF, HID,
        nullptr, (long long)HID_RF, nullptr, h1_hi, h1_lo);

    // 7) tail1 logits: h1 @ decode1^T (K=256), scatter rows1 -> out1
    gemm_mma<<<dim3((N_T1 + BN - 1) / BN, mb), 256>>>(
        h1_hi, h1_lo, HID_RF, nullptr, p_cnt1, B,
        d1_hi, d1_lo, HID_RF, N_T1, HID_RF,
        out1, (long long)N_T1, p_rows1, nullptr, nullptr);

    // 8) zero inactive rows exactly once
    zero0_k<<<B, 256>>>(targets, out0);
    zero1_k<<<B, 256>>>(targets, out1);

    (void)n_in; (void)out_size;
}